// round 2
// baseline (speedup 1.0000x reference)
#include <cuda_runtime.h>

// Problem dims (fixed by the dataset)
#define MM 32768   // B*S = 8*4096
#define KK 1024    // D
#define NN 1024    // O
#define RANK 16
#define NBR 5      // 1 shared + 4 tasks

// Scratch for XA = x @ [A_sh; A_tasks]^T  -> [MM][80]
// col layout: cols 0..15 = shared branch, cols 16+t*16+r = task t
__device__ float g_XA[(size_t)MM * 80];

// ---------------------------------------------------------------------------
// Kernel 1: XA[m][c] = sum_d x[m][d] * A_all[c][d]   (skinny GEMM, N=80)
// Block: 128 rows x 80 cols, 256 threads, each thread 8 rows x 5 cols.
// ---------------------------------------------------------------------------
__global__ void __launch_bounds__(256, 1)
xa_kernel(const float* __restrict__ x,
          const float* __restrict__ A_sh,
          const float* __restrict__ A_tasks)
{
    __shared__ float xs[32][132];   // [k][m], padded
    __shared__ float as_[80][36];   // [col][k], padded

    const int m0  = blockIdx.x * 128;
    const int tid = threadIdx.x;
    const int tc  = tid & 15;   // col group: cols tc*5 .. tc*5+4
    const int tr  = tid >> 4;   // row group: rows tr*8 .. tr*8+7

    float acc[8][5];
#pragma unroll
    for (int i = 0; i < 8; ++i)
#pragma unroll
        for (int j = 0; j < 5; ++j) acc[i][j] = 0.f;

    for (int k0 = 0; k0 < KK; k0 += 32) {
        __syncthreads();
        // x tile: 128 rows x 32 k, stored transposed xs[k][m]
#pragma unroll
        for (int c = 0; c < 4; ++c) {
            int i = tid * 4 + c * 1024;
            int row = i >> 5, kq = i & 31;
            float4 v = *(const float4*)(x + (size_t)(m0 + row) * KK + k0 + kq);
            xs[kq + 0][row] = v.x; xs[kq + 1][row] = v.y;
            xs[kq + 2][row] = v.z; xs[kq + 3][row] = v.w;
        }
        // A tile: 80 rows x 32 k, stored as_[col][k]
        for (int i = tid; i < 80 * 32; i += 256) {
            int col = i >> 5, kq = i & 31;
            const float* Ar = (col < 16) ? (A_sh + (size_t)col * KK)
                                         : (A_tasks + (size_t)(col - 16) * KK);
            as_[col][kq] = Ar[k0 + kq];
        }
        __syncthreads();

#pragma unroll 8
        for (int kq = 0; kq < 32; ++kq) {
            float xv[8], av[5];
#pragma unroll
            for (int i = 0; i < 8; ++i) xv[i] = xs[kq][tr * 8 + i];
#pragma unroll
            for (int j = 0; j < 5; ++j) av[j] = as_[tc * 5 + j][kq];
#pragma unroll
            for (int i = 0; i < 8; ++i)
#pragma unroll
                for (int j = 0; j < 5; ++j) acc[i][j] += xv[i] * av[j];
        }
    }

#pragma unroll
    for (int i = 0; i < 8; ++i)
#pragma unroll
        for (int j = 0; j < 5; ++j)
            g_XA[(size_t)(m0 + tr * 8 + i) * 80 + tc * 5 + j] = acc[i][j];
}

// ---------------------------------------------------------------------------
// Kernel 2: fused main GEMM + 5-branch LoRA epilogue.
// Per 128x128 tile:  C = x_tile @ W_tile^T + b           (K = 1024)
//   then for each branch br: out_br = C + s_br * XA_br_tile @ Bbr_tile^T
//   (rank-16 mini K-loop reusing the same smem staging buffers)
// ---------------------------------------------------------------------------
__global__ void __launch_bounds__(256, 1)
main_kernel(const float* __restrict__ x,
            const float* __restrict__ W,
            const float* __restrict__ bias,
            const float* __restrict__ B_sh,
            const float* __restrict__ B_tasks,
            const float* __restrict__ tscale,
            float* __restrict__ out)
{
    __shared__ float As[32][132];   // [k][m]
    __shared__ float Bs[32][132];   // [k][n]

    const int n0  = blockIdx.x * 128;
    const int m0  = blockIdx.y * 128;
    const int tid = threadIdx.x;
    const int tx  = tid & 15;
    const int ty  = tid >> 4;
    const int tm  = ty * 8;
    const int tn  = tx * 8;

    float acc[8][8];
#pragma unroll
    for (int i = 0; i < 8; ++i)
#pragma unroll
        for (int j = 0; j < 8; ++j) acc[i][j] = 0.f;

    // ---- main K loop ----
    for (int k0 = 0; k0 < KK; k0 += 32) {
        __syncthreads();
#pragma unroll
        for (int c = 0; c < 4; ++c) {
            int i = tid * 4 + c * 1024;
            int row = i >> 5, kq = i & 31;
            float4 va = *(const float4*)(x + (size_t)(m0 + row) * KK + k0 + kq);
            As[kq + 0][row] = va.x; As[kq + 1][row] = va.y;
            As[kq + 2][row] = va.z; As[kq + 3][row] = va.w;
            float4 vb = *(const float4*)(W + (size_t)(n0 + row) * KK + k0 + kq);
            Bs[kq + 0][row] = vb.x; Bs[kq + 1][row] = vb.y;
            Bs[kq + 2][row] = vb.z; Bs[kq + 3][row] = vb.w;
        }
        __syncthreads();

#pragma unroll 8
        for (int kq = 0; kq < 32; ++kq) {
            float a[8], bb[8];
            *(float4*)&a[0]  = *(const float4*)&As[kq][tm];
            *(float4*)&a[4]  = *(const float4*)&As[kq][tm + 4];
            *(float4*)&bb[0] = *(const float4*)&Bs[kq][tn];
            *(float4*)&bb[4] = *(const float4*)&Bs[kq][tn + 4];
#pragma unroll
            for (int i = 0; i < 8; ++i)
#pragma unroll
                for (int j = 0; j < 8; ++j) acc[i][j] += a[i] * bb[j];
        }
    }

    // ---- bias (applies to pretrained, i.e. to all 5 outputs) ----
    {
        float bv[8];
#pragma unroll
        for (int j = 0; j < 8; ++j) bv[j] = bias[n0 + tn + j];
#pragma unroll
        for (int i = 0; i < 8; ++i)
#pragma unroll
            for (int j = 0; j < 8; ++j) acc[i][j] += bv[j];
    }

    // ---- per-branch rank-16 epilogue ----
    for (int br = 0; br < NBR; ++br) {
        __syncthreads();
        // XA tile for this branch: 128 rows x 16 -> As[r][m]
#pragma unroll
        for (int c = 0; c < 2; ++c) {
            int i = tid * 4 + c * 1024;
            int row = i >> 4, rr = i & 15;
            float4 v = *(const float4*)(g_XA + (size_t)(m0 + row) * 80 + br * 16 + rr);
            As[rr + 0][row] = v.x; As[rr + 1][row] = v.y;
            As[rr + 2][row] = v.z; As[rr + 3][row] = v.w;
        }
        // B tile for this branch: 128 n-rows x 16 -> Bs[r][n]
        const float* Bp = (br == 0) ? B_sh
                                    : (B_tasks + (size_t)(br - 1) * NN * RANK);
#pragma unroll
        for (int c = 0; c < 2; ++c) {
            int i = tid * 4 + c * 1024;
            int row = i >> 4, rr = i & 15;
            float4 v = *(const float4*)(Bp + (size_t)(n0 + row) * RANK + rr);
            Bs[rr + 0][row] = v.x; Bs[rr + 1][row] = v.y;
            Bs[rr + 2][row] = v.z; Bs[rr + 3][row] = v.w;
        }
        const float s = (br == 0) ? 1.0f : tscale[br - 1];
        __syncthreads();

        float c2[8][8];
#pragma unroll
        for (int i = 0; i < 8; ++i)
#pragma unroll
            for (int j = 0; j < 8; ++j) c2[i][j] = 0.f;

#pragma unroll
        for (int r = 0; r < RANK; ++r) {
            float a[8], bb[8];
            *(float4*)&a[0]  = *(const float4*)&As[r][tm];
            *(float4*)&a[4]  = *(const float4*)&As[r][tm + 4];
            *(float4*)&bb[0] = *(const float4*)&Bs[r][tn];
            *(float4*)&bb[4] = *(const float4*)&Bs[r][tn + 4];
#pragma unroll
            for (int i = 0; i < 8; ++i)
#pragma unroll
                for (int j = 0; j < 8; ++j) c2[i][j] += a[i] * bb[j];
        }

        float* op = out + (size_t)br * MM * NN + (size_t)(m0 + tm) * NN + (n0 + tn);
#pragma unroll
        for (int i = 0; i < 8; ++i) {
            float4 w0, w1;
            w0.x = acc[i][0] + s * c2[i][0];
            w0.y = acc[i][1] + s * c2[i][1];
            w0.z = acc[i][2] + s * c2[i][2];
            w0.w = acc[i][3] + s * c2[i][3];
            w1.x = acc[i][4] + s * c2[i][4];
            w1.y = acc[i][5] + s * c2[i][5];
            w1.z = acc[i][6] + s * c2[i][6];
            w1.w = acc[i][7] + s * c2[i][7];
            *(float4*)(op + (size_t)i * NN)     = w0;
            *(float4*)(op + (size_t)i * NN + 4) = w1;
        }
    }
}

// ---------------------------------------------------------------------------
extern "C" void kernel_launch(void* const* d_in, const int* in_sizes, int n_in,
                              void* d_out, int out_size)
{
    const float* x        = (const float*)d_in[0];
    const float* W        = (const float*)d_in[1];
    const float* b        = (const float*)d_in[2];
    const float* A_sh     = (const float*)d_in[3];
    const float* B_sh     = (const float*)d_in[4];
    const float* A_tasks  = (const float*)d_in[5];
    const float* B_tasks  = (const float*)d_in[6];
    const float* tscale   = (const float*)d_in[7];
    float* out            = (float*)d_out;

    xa_kernel<<<MM / 128, 256>>>(x, A_sh, A_tasks);

    dim3 grid(NN / 128, MM / 128);
    main_kernel<<<grid, 256>>>(x, W, b, B_sh, B_tasks, tscale, out);
}

// round 5
// speedup vs baseline: 2.5734x; 2.5734x over previous
#include <cuda_runtime.h>
#include <cuda_bf16.h>
#include <cstdint>

#define MM 32768
#define KK 1024
#define NN 1024
#define NBR 5

// ------------------- static device scratch ---------------------------------
__device__ __nv_bfloat16 g_xhi[(size_t)MM * KK];
__device__ __nv_bfloat16 g_xlo[(size_t)MM * KK];
__device__ __nv_bfloat16 g_whi[(size_t)NN * KK];
__device__ __nv_bfloat16 g_wlo[(size_t)NN * KK];
__device__ __nv_bfloat16 g_abf[80 * KK];                 // [80][1024] bf16
__device__ __nv_bfloat16 g_bc[(size_t)NBR * NN * 16];    // [br][n][16], scale folded
__device__ __nv_bfloat16 g_xa[(size_t)MM * 80];          // [m][80] bf16

// ------------------- helpers -----------------------------------------------
__device__ __forceinline__ uint32_t s2u(const void* p) {
    uint32_t a;
    asm("{ .reg .u64 t; cvta.to.shared.u64 t, %1; cvt.u32.u64 %0, t; }" : "=r"(a) : "l"(p));
    return a;
}
#define CPA16(d, s) asm volatile("cp.async.cg.shared.global [%0], [%1], 16;" :: "r"(d), "l"(s))
#define CPCOMMIT()  asm volatile("cp.async.commit_group;")
#define CPWAIT(n)   asm volatile("cp.async.wait_group %0;" :: "n"(n))

__device__ __forceinline__ void ldsm4(uint32_t* r, uint32_t a) {
    asm volatile("ldmatrix.sync.aligned.m8n8.x4.shared.b16 {%0,%1,%2,%3}, [%4];"
                 : "=r"(r[0]), "=r"(r[1]), "=r"(r[2]), "=r"(r[3]) : "r"(a));
}
__device__ __forceinline__ void ldsm2(uint32_t* r, uint32_t a) {
    asm volatile("ldmatrix.sync.aligned.m8n8.x2.shared.b16 {%0,%1}, [%2];"
                 : "=r"(r[0]), "=r"(r[1]) : "r"(a));
}
__device__ __forceinline__ void mma16816(float* c, const uint32_t* a, uint32_t b0, uint32_t b1) {
    asm volatile("mma.sync.aligned.m16n8k16.row.col.f32.bf16.bf16.f32 "
                 "{%0,%1,%2,%3},{%4,%5,%6,%7},{%8,%9},{%0,%1,%2,%3};"
                 : "+f"(c[0]), "+f"(c[1]), "+f"(c[2]), "+f"(c[3])
                 : "r"(a[0]), "r"(a[1]), "r"(a[2]), "r"(a[3]), "r"(b0), "r"(b1));
}
__device__ __forceinline__ void split2(float v, __nv_bfloat16& h, __nv_bfloat16& l) {
    h = __float2bfloat16(v);
    l = __float2bfloat16(v - __bfloat162float(h));
}

// ------------------- prep kernels ------------------------------------------
__global__ void __launch_bounds__(256) split_x_k(const float* __restrict__ x) {
    size_t i = ((size_t)blockIdx.x * 256 + threadIdx.x) * 4;
    float4 v = *(const float4*)(x + i);
    float f[4] = {v.x, v.y, v.z, v.w};
    __nv_bfloat162 h2[2], l2[2];
#pragma unroll
    for (int j = 0; j < 2; ++j) {
        __nv_bfloat16 h0, l0, h1, l1;
        split2(f[2 * j], h0, l0); split2(f[2 * j + 1], h1, l1);
        h2[j].x = h0; h2[j].y = h1; l2[j].x = l0; l2[j].y = l1;
    }
    ((__nv_bfloat162*)(g_xhi + i))[0] = h2[0]; ((__nv_bfloat162*)(g_xhi + i))[1] = h2[1];
    ((__nv_bfloat162*)(g_xlo + i))[0] = l2[0]; ((__nv_bfloat162*)(g_xlo + i))[1] = l2[1];
}
__global__ void __launch_bounds__(256) split_w_k(const float* __restrict__ w) {
    size_t i = ((size_t)blockIdx.x * 256 + threadIdx.x) * 4;
    float4 v = *(const float4*)(w + i);
    float f[4] = {v.x, v.y, v.z, v.w};
    __nv_bfloat162 h2[2], l2[2];
#pragma unroll
    for (int j = 0; j < 2; ++j) {
        __nv_bfloat16 h0, l0, h1, l1;
        split2(f[2 * j], h0, l0); split2(f[2 * j + 1], h1, l1);
        h2[j].x = h0; h2[j].y = h1; l2[j].x = l0; l2[j].y = l1;
    }
    ((__nv_bfloat162*)(g_whi + i))[0] = h2[0]; ((__nv_bfloat162*)(g_whi + i))[1] = h2[1];
    ((__nv_bfloat162*)(g_wlo + i))[0] = l2[0]; ((__nv_bfloat162*)(g_wlo + i))[1] = l2[1];
}
__global__ void __launch_bounds__(256) conv_a_k(const float* __restrict__ A_sh,
                                                const float* __restrict__ A_tasks) {
    size_t i = ((size_t)blockIdx.x * 256 + threadIdx.x) * 4;   // < 81920
    const float* src = (i < 16384) ? (A_sh + i) : (A_tasks + (i - 16384));
    float4 v = *(const float4*)src;
    __nv_bfloat162 a{__float2bfloat16(v.x), __float2bfloat16(v.y)};
    __nv_bfloat162 b{__float2bfloat16(v.z), __float2bfloat16(v.w)};
    ((__nv_bfloat162*)(g_abf + i))[0] = a; ((__nv_bfloat162*)(g_abf + i))[1] = b;
}
__global__ void __launch_bounds__(256) prep_bc_k(const float* __restrict__ B_sh,
                                                 const float* __restrict__ B_tasks,
                                                 const float* __restrict__ ts) {
    int id = blockIdx.x * 256 + threadIdx.x;   // < 5120
    int br = id >> 10, n = id & 1023;
    const float* row = (br == 0) ? (B_sh + (size_t)n * 16)
                                 : (B_tasks + ((size_t)(br - 1) * NN + n) * 16);
    float s = (br == 0) ? 1.0f : ts[br - 1];
    __nv_bfloat16* dst = g_bc + ((size_t)br * NN + n) * 16;
#pragma unroll
    for (int r = 0; r < 16; ++r) dst[r] = __float2bfloat16(s * row[r]);
}

// ------------------- XA kernel (HMMA, single bf16) --------------------------
// XA[m][c] = sum_d x_hi[m][d] * A_bf[c][d].  CTA tile 128m x 80n, 8 warps.
#define XA_STG 26624

__device__ __forceinline__ void xa_load(int c, uint32_t sb, int m0, int tid) {
    int k0 = c << 6;
#pragma unroll
    for (int i = 0; i < 7; ++i) {
        int id = tid + (i << 8);
        if (id < 1024) {
            int row = id >> 3, c16 = id & 7;
            CPA16(sb + row * 128 + ((c16 ^ (row & 7)) << 4),
                  (const char*)(g_xhi + (size_t)(m0 + row) * KK + k0) + c16 * 16);
        } else if (id < 1664) {
            int id2 = id - 1024;
            int row = id2 >> 3, c16 = id2 & 7;
            CPA16(sb + 16384 + row * 128 + ((c16 ^ (row & 7)) << 4),
                  (const char*)(g_abf + (size_t)row * KK + k0) + c16 * 16);
        }
    }
}

__global__ void __launch_bounds__(256, 1) xa_kernel() {
    extern __shared__ char sm[];
    const uint32_t base = s2u(sm);
    const int tid = threadIdx.x, wid = tid >> 5, l = tid & 31;
    const int m0 = blockIdx.x * 128;
    const int wm = wid & 3, wn = wid >> 2;

    float acc[2][5][4];
#pragma unroll
    for (int i = 0; i < 2; ++i)
#pragma unroll
        for (int j = 0; j < 5; ++j)
#pragma unroll
            for (int k = 0; k < 4; ++k) acc[i][j][k] = 0.f;

    xa_load(0, base, m0, tid); CPCOMMIT();
    xa_load(1, base + XA_STG, m0, tid); CPCOMMIT();

    const uint32_t arow  = (uint32_t)((wm * 32 + (l & 15)) * 128);
    const uint32_t brow  = (uint32_t)((wn * 40 + (l & 15)) * 128) + 16384;
    const uint32_t brow2 = (uint32_t)((wn * 40 + 32 + (l & 7)) * 128) + 16384;
    const uint32_t ax = (uint32_t)(l & 7);
    const uint32_t hi16 = (uint32_t)(l >> 4);
    const uint32_t sel2 = (uint32_t)((l >> 3) & 1);

    for (int c = 0; c < 16; ++c) {
        uint32_t sb = base + (c % 3) * XA_STG;
        if (c == 15) { CPWAIT(0); } else { CPWAIT(1); }
        __syncthreads();
        if (c + 2 < 16) { xa_load(c + 2, base + ((c + 2) % 3) * XA_STG, m0, tid); CPCOMMIT(); }
#pragma unroll
        for (int ks = 0; ks < 4; ++ks) {
            uint32_t kc = (uint32_t)(ks * 2);
            uint32_t a[2][4], b[2][4], b2[2];
#pragma unroll
            for (int fi = 0; fi < 2; ++fi)
                ldsm4(a[fi], sb + arow + fi * 2048 + (((kc + hi16) ^ ax) << 4));
#pragma unroll
            for (int g = 0; g < 2; ++g)
                ldsm4(b[g], sb + brow + g * 2048 + (((kc + hi16) ^ ax) << 4));
            ldsm2(b2, sb + brow2 + (((kc + sel2) ^ ax) << 4));
#pragma unroll
            for (int fi = 0; fi < 2; ++fi) {
#pragma unroll
                for (int nf = 0; nf < 4; ++nf)
                    mma16816(acc[fi][nf], a[fi], b[nf >> 1][nf & 1], b[nf >> 1][(nf & 1) + 2]);
                mma16816(acc[fi][4], a[fi], b2[0], b2[1]);
            }
        }
    }
    __syncthreads();

#pragma unroll
    for (int fi = 0; fi < 2; ++fi)
#pragma unroll
        for (int j = 0; j < 5; ++j) {
            int n = wn * 40 + j * 8 + 2 * (l & 3);
            int mlo = m0 + wm * 32 + fi * 16 + (l >> 2);
            __nv_bfloat162 v0{__float2bfloat16(acc[fi][j][0]), __float2bfloat16(acc[fi][j][1])};
            __nv_bfloat162 v1{__float2bfloat16(acc[fi][j][2]), __float2bfloat16(acc[fi][j][3])};
            *(__nv_bfloat162*)(g_xa + (size_t)mlo * 80 + n) = v0;
            *(__nv_bfloat162*)(g_xa + (size_t)(mlo + 8) * 80 + n) = v1;
        }
}

// ------------------- main kernel --------------------------------------------
// CTA tile 128m x 128n; 8 warps = 2(m) x 4(n); warp tile 64m x 32n.
// K' = 3072 (3-term hi/lo), chunks of 64: t0 = xhi*Whi, t1 = xlo*Whi, t2 = xhi*Wlo.
#define M_STG 32768

__device__ __forceinline__ void main_load(int c, uint32_t sb, int m0, int n0, int tid) {
    int t = c >> 4, k0 = (c & 15) << 6;
    const __nv_bfloat16* xs = (t == 1) ? g_xlo : g_xhi;
    const __nv_bfloat16* ws = (t == 2) ? g_wlo : g_whi;
#pragma unroll
    for (int i = 0; i < 4; ++i) {
        int id = tid + (i << 8);
        int row = id >> 3, c16 = id & 7;
        uint32_t dst = sb + row * 128 + ((c16 ^ (row & 7)) << 4);
        CPA16(dst, (const char*)(xs + (size_t)(m0 + row) * KK + k0) + c16 * 16);
        CPA16(dst + 16384, (const char*)(ws + (size_t)(n0 + row) * KK + k0) + c16 * 16);
    }
}

__device__ __forceinline__ void corr_load(int br, uint32_t ep, int m0, int n0, int tid) {
    int row = tid >> 1, ch = tid & 1;
    uint32_t slot = (uint32_t)((((row & 3) * 2 + ch) ^ ((row >> 2) & 1)));
    uint32_t off = (uint32_t)((row >> 2) * 128) + slot * 16;
    CPA16(ep + off, (const char*)(g_xa + (size_t)(m0 + row) * 80 + br * 16) + ch * 16);
    CPA16(ep + 4096 + off, (const char*)(g_bc + ((size_t)br * NN + n0 + row) * 16) + ch * 16);
}

__global__ void __launch_bounds__(256, 1) main_kernel(const float* __restrict__ bias,
                                                      float* __restrict__ out) {
    extern __shared__ char sm[];
    const uint32_t base = s2u(sm);
    const int tid = threadIdx.x, wid = tid >> 5, l = tid & 31;
    const int n0 = blockIdx.x * 128, m0 = blockIdx.y * 128;
    const int wm = wid & 1, wn = wid >> 1;

    float acc[4][4][4];
#pragma unroll
    for (int i = 0; i < 4; ++i)
#pragma unroll
        for (int j = 0; j < 4; ++j)
#pragma unroll
            for (int k = 0; k < 4; ++k) acc[i][j][k] = 0.f;

    main_load(0, base, m0, n0, tid); CPCOMMIT();
    main_load(1, base + M_STG, m0, n0, tid); CPCOMMIT();

    const uint32_t arow = (uint32_t)((wm * 64 + (l & 15)) * 128);
    const uint32_t brow = (uint32_t)((wn * 32 + (l & 15)) * 128) + 16384;
    const uint32_t ax = (uint32_t)(l & 7);
    const uint32_t hi16 = (uint32_t)(l >> 4);

    for (int c = 0; c < 48; ++c) {
        uint32_t sb = base + (c % 3) * M_STG;
        if (c == 47) { CPWAIT(0); } else { CPWAIT(1); }
        __syncthreads();
        if (c + 2 < 48) { main_load(c + 2, base + ((c + 2) % 3) * M_STG, m0, n0, tid); CPCOMMIT(); }
#pragma unroll
        for (int ks = 0; ks < 4; ++ks) {
            uint32_t kc = (uint32_t)(ks * 2);
            uint32_t a[4][4], b[2][4];
#pragma unroll
            for (int fi = 0; fi < 4; ++fi)
                ldsm4(a[fi], sb + arow + fi * 2048 + (((kc + hi16) ^ ax) << 4));
#pragma unroll
            for (int g = 0; g < 2; ++g)
                ldsm4(b[g], sb + brow + g * 2048 + (((kc + hi16) ^ ax) << 4));
#pragma unroll
            for (int fi = 0; fi < 4; ++fi)
#pragma unroll
                for (int nf = 0; nf < 4; ++nf)
                    mma16816(acc[fi][nf], a[fi], b[nf >> 1][nf & 1], b[nf >> 1][(nf & 1) + 2]);
        }
    }
    __syncthreads();

    // fold bias into accumulators
#pragma unroll
    for (int j = 0; j < 4; ++j) {
        float2 bv = *(const float2*)(bias + n0 + wn * 32 + j * 8 + 2 * (l & 3));
#pragma unroll
        for (int fi = 0; fi < 4; ++fi) {
            acc[fi][j][0] += bv.x; acc[fi][j][1] += bv.y;
            acc[fi][j][2] += bv.x; acc[fi][j][3] += bv.y;
        }
    }

    // ---- per-branch rank-16 correction + store ----
    const uint32_t ep = base;   // reuse stage 0 smem: xa_s @ ep, bc_s @ ep+4096
    corr_load(0, ep, m0, n0, tid); CPCOMMIT();

    for (int br = 0; br < NBR; ++br) {
        CPWAIT(0);
        __syncthreads();
        float corr[4][4][4];
        uint32_t a[4][4], b[2][4];
#pragma unroll
        for (int fi = 0; fi < 4; ++fi) {
            int row = wm * 64 + fi * 16 + (l & 15);
            uint32_t ad = ep + (uint32_t)((row >> 2) * 128) +
                          (((uint32_t)((row & 3) * 2) + hi16) ^ (uint32_t)((row >> 2) & 1)) * 16;
            ldsm4(a[fi], ad);
        }
#pragma unroll
        for (int g = 0; g < 2; ++g) {
            int row = wn * 32 + g * 16 + (l & 15);
            uint32_t ad = ep + 4096 + (uint32_t)((row >> 2) * 128) +
                          (((uint32_t)((row & 3) * 2) + hi16) ^ (uint32_t)((row >> 2) & 1)) * 16;
            ldsm4(b[g], ad);
        }
#pragma unroll
        for (int fi = 0; fi < 4; ++fi)
#pragma unroll
            for (int nf = 0; nf < 4; ++nf) {
#pragma unroll
                for (int k = 0; k < 4; ++k) corr[fi][nf][k] = 0.f;
                mma16816(corr[fi][nf], a[fi], b[nf >> 1][nf & 1], b[nf >> 1][(nf & 1) + 2]);
            }
        __syncthreads();   // all warps done reading tiles
        if (br < 4) { corr_load(br + 1, ep, m0, n0, tid); CPCOMMIT(); }

        float* ob = out + (size_t)br * MM * NN;
#pragma unroll
        for (int fi = 0; fi < 4; ++fi) {
            int mlo = m0 + wm * 64 + fi * 16 + (l >> 2);
#pragma unroll
            for (int j = 0; j < 4; ++j) {
                int n = n0 + wn * 32 + j * 8 + 2 * (l & 3);
                float2 v0{acc[fi][j][0] + corr[fi][j][0], acc[fi][j][1] + corr[fi][j][1]};
                float2 v1{acc[fi][j][2] + corr[fi][j][2], acc[fi][j][3] + corr[fi][j][3]};
                *(float2*)(ob + (size_t)mlo * NN + n) = v0;
                *(float2*)(ob + (size_t)(mlo + 8) * NN + n) = v1;
            }
        }
    }
}

// ------------------- launcher -----------------------------------------------
extern "C" void kernel_launch(void* const* d_in, const int* in_sizes, int n_in,
                              void* d_out, int out_size)
{
    const float* x       = (const float*)d_in[0];
    const float* W       = (const float*)d_in[1];
    const float* b       = (const float*)d_in[2];
    const float* A_sh    = (const float*)d_in[3];
    const float* B_sh    = (const float*)d_in[4];
    const float* A_tasks = (const float*)d_in[5];
    const float* B_tasks = (const float*)d_in[6];
    const float* tscale  = (const float*)d_in[7];
    float* out           = (float*)d_out;

    static bool attr_done = false;
    if (!attr_done) {
        cudaFuncSetAttribute(main_kernel, cudaFuncAttributeMaxDynamicSharedMemorySize, 3 * M_STG);
        cudaFuncSetAttribute(xa_kernel,  cudaFuncAttributeMaxDynamicSharedMemorySize, 3 * XA_STG);
        attr_done = true;
    }

    split_x_k<<<MM * KK / 1024, 256>>>(x);
    split_w_k<<<NN * KK / 1024, 256>>>(W);
    conv_a_k<<<80, 256>>>(A_sh, A_tasks);
    prep_bc_k<<<20, 256>>>(B_sh, B_tasks, tscale);
    xa_kernel<<<MM / 128, 256, 3 * XA_STG>>>();
    main_kernel<<<dim3(NN / 128, MM / 128), 256, 3 * M_STG>>>(b, out);
}

// round 6
// speedup vs baseline: 2.8910x; 1.1234x over previous
#include <cuda_runtime.h>
#include <cuda_bf16.h>
#include <cstdint>

#define MM 32768
#define KK 1024
#define NN 1024
#define NBR 5

// ------------------- static device scratch ---------------------------------
__device__ __nv_bfloat16 g_xhi[(size_t)MM * KK];
__device__ __nv_bfloat16 g_xlo[(size_t)MM * KK];
__device__ __nv_bfloat16 g_whi[(size_t)NN * KK];
__device__ __nv_bfloat16 g_wlo[(size_t)NN * KK];
__device__ __nv_bfloat16 g_abf[80 * KK];                 // [80][1024] bf16
__device__ __nv_bfloat16 g_bc[(size_t)NBR * NN * 16];    // [br][n][16], scale folded
__device__ __nv_bfloat16 g_xa[(size_t)MM * 80];          // [m][80] bf16

// ------------------- helpers -----------------------------------------------
__device__ __forceinline__ uint32_t s2u(const void* p) {
    uint32_t a;
    asm("{ .reg .u64 t; cvta.to.shared.u64 t, %1; cvt.u32.u64 %0, t; }" : "=r"(a) : "l"(p));
    return a;
}
#define CPA16(d, s) asm volatile("cp.async.cg.shared.global [%0], [%1], 16;" :: "r"(d), "l"(s))
#define CPCOMMIT()  asm volatile("cp.async.commit_group;")
#define CPWAIT(n)   asm volatile("cp.async.wait_group %0;" :: "n"(n))

__device__ __forceinline__ void ldsm4(uint32_t* r, uint32_t a) {
    asm volatile("ldmatrix.sync.aligned.m8n8.x4.shared.b16 {%0,%1,%2,%3}, [%4];"
                 : "=r"(r[0]), "=r"(r[1]), "=r"(r[2]), "=r"(r[3]) : "r"(a));
}
__device__ __forceinline__ void ldsm2(uint32_t* r, uint32_t a) {
    asm volatile("ldmatrix.sync.aligned.m8n8.x2.shared.b16 {%0,%1}, [%2];"
                 : "=r"(r[0]), "=r"(r[1]) : "r"(a));
}
__device__ __forceinline__ void mma16816(float* c, const uint32_t* a, uint32_t b0, uint32_t b1) {
    asm volatile("mma.sync.aligned.m16n8k16.row.col.f32.bf16.bf16.f32 "
                 "{%0,%1,%2,%3},{%4,%5,%6,%7},{%8,%9},{%0,%1,%2,%3};"
                 : "+f"(c[0]), "+f"(c[1]), "+f"(c[2]), "+f"(c[3])
                 : "r"(a[0]), "r"(a[1]), "r"(a[2]), "r"(a[3]), "r"(b0), "r"(b1));
}
__device__ __forceinline__ void split2(float v, __nv_bfloat16& h, __nv_bfloat16& l) {
    h = __float2bfloat16(v);
    l = __float2bfloat16(v - __bfloat162float(h));
}

// ------------------- prep kernels ------------------------------------------
__global__ void __launch_bounds__(256) split_x_k(const float* __restrict__ x) {
    size_t i = ((size_t)blockIdx.x * 256 + threadIdx.x) * 4;
    float4 v = *(const float4*)(x + i);
    float f[4] = {v.x, v.y, v.z, v.w};
    __nv_bfloat162 h2[2], l2[2];
#pragma unroll
    for (int j = 0; j < 2; ++j) {
        __nv_bfloat16 h0, l0, h1, l1;
        split2(f[2 * j], h0, l0); split2(f[2 * j + 1], h1, l1);
        h2[j].x = h0; h2[j].y = h1; l2[j].x = l0; l2[j].y = l1;
    }
    ((__nv_bfloat162*)(g_xhi + i))[0] = h2[0]; ((__nv_bfloat162*)(g_xhi + i))[1] = h2[1];
    ((__nv_bfloat162*)(g_xlo + i))[0] = l2[0]; ((__nv_bfloat162*)(g_xlo + i))[1] = l2[1];
}
__global__ void __launch_bounds__(256) split_w_k(const float* __restrict__ w) {
    size_t i = ((size_t)blockIdx.x * 256 + threadIdx.x) * 4;
    float4 v = *(const float4*)(w + i);
    float f[4] = {v.x, v.y, v.z, v.w};
    __nv_bfloat162 h2[2], l2[2];
#pragma unroll
    for (int j = 0; j < 2; ++j) {
        __nv_bfloat16 h0, l0, h1, l1;
        split2(f[2 * j], h0, l0); split2(f[2 * j + 1], h1, l1);
        h2[j].x = h0; h2[j].y = h1; l2[j].x = l0; l2[j].y = l1;
    }
    ((__nv_bfloat162*)(g_whi + i))[0] = h2[0]; ((__nv_bfloat162*)(g_whi + i))[1] = h2[1];
    ((__nv_bfloat162*)(g_wlo + i))[0] = l2[0]; ((__nv_bfloat162*)(g_wlo + i))[1] = l2[1];
}
__global__ void __launch_bounds__(256) conv_a_k(const float* __restrict__ A_sh,
                                                const float* __restrict__ A_tasks) {
    size_t i = ((size_t)blockIdx.x * 256 + threadIdx.x) * 4;   // < 81920
    const float* src = (i < 16384) ? (A_sh + i) : (A_tasks + (i - 16384));
    float4 v = *(const float4*)src;
    __nv_bfloat162 a{__float2bfloat16(v.x), __float2bfloat16(v.y)};
    __nv_bfloat162 b{__float2bfloat16(v.z), __float2bfloat16(v.w)};
    ((__nv_bfloat162*)(g_abf + i))[0] = a; ((__nv_bfloat162*)(g_abf + i))[1] = b;
}
__global__ void __launch_bounds__(256) prep_bc_k(const float* __restrict__ B_sh,
                                                 const float* __restrict__ B_tasks,
                                                 const float* __restrict__ ts) {
    int id = blockIdx.x * 256 + threadIdx.x;   // < 5120
    int br = id >> 10, n = id & 1023;
    const float* row = (br == 0) ? (B_sh + (size_t)n * 16)
                                 : (B_tasks + ((size_t)(br - 1) * NN + n) * 16);
    float s = (br == 0) ? 1.0f : ts[br - 1];
    __nv_bfloat16* dst = g_bc + ((size_t)br * NN + n) * 16;
#pragma unroll
    for (int r = 0; r < 16; ++r) dst[r] = __float2bfloat16(s * row[r]);
}

// ------------------- XA kernel (HMMA, single bf16) --------------------------
#define XA_STG 26624

__device__ __forceinline__ void xa_load(int c, uint32_t sb, int m0, int tid) {
    int k0 = c << 6;
#pragma unroll
    for (int i = 0; i < 7; ++i) {
        int id = tid + (i << 8);
        if (id < 1024) {
            int row = id >> 3, c16 = id & 7;
            CPA16(sb + row * 128 + ((c16 ^ (row & 7)) << 4),
                  (const char*)(g_xhi + (size_t)(m0 + row) * KK + k0) + c16 * 16);
        } else if (id < 1664) {
            int id2 = id - 1024;
            int row = id2 >> 3, c16 = id2 & 7;
            CPA16(sb + 16384 + row * 128 + ((c16 ^ (row & 7)) << 4),
                  (const char*)(g_abf + (size_t)row * KK + k0) + c16 * 16);
        }
    }
}

__global__ void __launch_bounds__(256, 1) xa_kernel() {
    extern __shared__ char sm[];
    const uint32_t base = s2u(sm);
    const int tid = threadIdx.x, wid = tid >> 5, l = tid & 31;
    const int m0 = blockIdx.x * 128;
    const int wm = wid & 3, wn = wid >> 2;

    float acc[2][5][4];
#pragma unroll
    for (int i = 0; i < 2; ++i)
#pragma unroll
        for (int j = 0; j < 5; ++j)
#pragma unroll
            for (int k = 0; k < 4; ++k) acc[i][j][k] = 0.f;

    xa_load(0, base, m0, tid); CPCOMMIT();
    xa_load(1, base + XA_STG, m0, tid); CPCOMMIT();

    const uint32_t arow  = (uint32_t)((wm * 32 + (l & 15)) * 128);
    const uint32_t brow  = (uint32_t)((wn * 40 + (l & 15)) * 128) + 16384;
    const uint32_t brow2 = (uint32_t)((wn * 40 + 32 + (l & 7)) * 128) + 16384;
    const uint32_t ax = (uint32_t)(l & 7);
    const uint32_t hi16 = (uint32_t)(l >> 4);
    const uint32_t sel2 = (uint32_t)((l >> 3) & 1);

    for (int c = 0; c < 16; ++c) {
        uint32_t sb = base + (c % 3) * XA_STG;
        if (c == 15) { CPWAIT(0); } else { CPWAIT(1); }
        __syncthreads();
        if (c + 2 < 16) { xa_load(c + 2, base + ((c + 2) % 3) * XA_STG, m0, tid); CPCOMMIT(); }
#pragma unroll
        for (int ks = 0; ks < 4; ++ks) {
            uint32_t kc = (uint32_t)(ks * 2);
            uint32_t a[2][4], b[2][4], b2[2];
#pragma unroll
            for (int fi = 0; fi < 2; ++fi)
                ldsm4(a[fi], sb + arow + fi * 2048 + (((kc + hi16) ^ ax) << 4));
#pragma unroll
            for (int g = 0; g < 2; ++g)
                ldsm4(b[g], sb + brow + g * 2048 + (((kc + hi16) ^ ax) << 4));
            ldsm2(b2, sb + brow2 + (((kc + sel2) ^ ax) << 4));
#pragma unroll
            for (int fi = 0; fi < 2; ++fi) {
#pragma unroll
                for (int nf = 0; nf < 4; ++nf)
                    mma16816(acc[fi][nf], a[fi], b[nf >> 1][nf & 1], b[nf >> 1][(nf & 1) + 2]);
                mma16816(acc[fi][4], a[fi], b2[0], b2[1]);
            }
        }
    }
    __syncthreads();

#pragma unroll
    for (int fi = 0; fi < 2; ++fi)
#pragma unroll
        for (int j = 0; j < 5; ++j) {
            int n = wn * 40 + j * 8 + 2 * (l & 3);
            int mlo = m0 + wm * 32 + fi * 16 + (l >> 2);
            __nv_bfloat162 v0{__float2bfloat16(acc[fi][j][0]), __float2bfloat16(acc[fi][j][1])};
            __nv_bfloat162 v1{__float2bfloat16(acc[fi][j][2]), __float2bfloat16(acc[fi][j][3])};
            *(__nv_bfloat162*)(g_xa + (size_t)mlo * 80 + n) = v0;
            *(__nv_bfloat162*)(g_xa + (size_t)(mlo + 8) * 80 + n) = v1;
        }
}

// ------------------- main kernel --------------------------------------------
// CTA: 512 threads, tile M=256(m) x N=128(n); 16 warps = 4(m) x 4(n); warp 64x32.
// K' = 3072: t0 = xhi*Whi, t1 = xlo*Whi, t2 = xhi*Wlo.  Stage: x 256x64 @ +0
// (32KB), W 128x64 @ +32768 (16KB).  3 stages x 48KB = 144KB smem.
#define M_STG 49152

__device__ __forceinline__ void main_load(int c, uint32_t sb, int m0, int n0, int tid) {
    int t = c >> 4, k0 = (c & 15) << 6;
    const __nv_bfloat16* xs = (t == 1) ? g_xlo : g_xhi;
    const __nv_bfloat16* ws = (t == 2) ? g_wlo : g_whi;
#pragma unroll
    for (int i = 0; i < 6; ++i) {
        int id = tid + (i << 9);
        if (id < 2048) {
            int row = id >> 3, c16 = id & 7;
            CPA16(sb + row * 128 + ((c16 ^ (row & 7)) << 4),
                  (const char*)(xs + (size_t)(m0 + row) * KK + k0) + c16 * 16);
        } else {
            int id2 = id - 2048;
            int row = id2 >> 3, c16 = id2 & 7;
            CPA16(sb + 32768 + row * 128 + ((c16 ^ (row & 7)) << 4),
                  (const char*)(ws + (size_t)(n0 + row) * KK + k0) + c16 * 16);
        }
    }
}

// correction staging: A (256x16 bf16, 8KB) @ ep, B (128x16, 4KB) @ ep+8192.
// 4 rows per 128B line, slot = ((row&3)*2+half) ^ ((row>>2)&1).
__device__ __forceinline__ void corr_load(int br, uint32_t ep, int m0, int n0, int tid) {
    int row = tid >> 1, ch = tid & 1;
    uint32_t slot = (uint32_t)(((row & 3) * 2 + ch) ^ ((row >> 2) & 1));
    uint32_t off = (uint32_t)((row >> 2) * 128) + slot * 16;
    CPA16(ep + off, (const char*)(g_xa + (size_t)(m0 + row) * 80 + br * 16) + ch * 16);
    if (tid < 256)
        CPA16(ep + 8192 + off, (const char*)(g_bc + ((size_t)br * NN + n0 + row) * 16) + ch * 16);
}

__global__ void __launch_bounds__(512, 1) main_kernel(const float* __restrict__ bias,
                                                      float* __restrict__ out) {
    extern __shared__ char sm[];
    const uint32_t base = s2u(sm);
    const int tid = threadIdx.x, wid = tid >> 5, l = tid & 31;
    const int n0 = blockIdx.x * 128, m0 = blockIdx.y * 256;
    const int wm = wid & 3, wn = wid >> 2;

    float acc[4][4][4];
#pragma unroll
    for (int i = 0; i < 4; ++i)
#pragma unroll
        for (int j = 0; j < 4; ++j)
#pragma unroll
            for (int k = 0; k < 4; ++k) acc[i][j][k] = 0.f;

    main_load(0, base, m0, n0, tid); CPCOMMIT();
    main_load(1, base + M_STG, m0, n0, tid); CPCOMMIT();

    const uint32_t arow = (uint32_t)((wm * 64 + (l & 15)) * 128);
    const uint32_t brow = (uint32_t)((wn * 32 + (l & 15)) * 128) + 32768;
    const uint32_t ax = (uint32_t)(l & 7);
    const uint32_t hi16 = (uint32_t)(l >> 4);

    for (int c = 0; c < 48; ++c) {
        uint32_t sb = base + (c % 3) * M_STG;
        if (c == 47) { CPWAIT(0); } else { CPWAIT(1); }
        __syncthreads();
        if (c + 2 < 48) { main_load(c + 2, base + ((c + 2) % 3) * M_STG, m0, n0, tid); CPCOMMIT(); }
#pragma unroll
        for (int ks = 0; ks < 4; ++ks) {
            uint32_t kc = (uint32_t)(ks * 2);
            uint32_t a[4][4], b[2][4];
#pragma unroll
            for (int fi = 0; fi < 4; ++fi)
                ldsm4(a[fi], sb + arow + fi * 2048 + (((kc + hi16) ^ ax) << 4));
#pragma unroll
            for (int g = 0; g < 2; ++g)
                ldsm4(b[g], sb + brow + g * 2048 + (((kc + hi16) ^ ax) << 4));
#pragma unroll
            for (int fi = 0; fi < 4; ++fi)
#pragma unroll
                for (int nf = 0; nf < 4; ++nf)
                    mma16816(acc[fi][nf], a[fi], b[nf >> 1][nf & 1], b[nf >> 1][(nf & 1) + 2]);
        }
    }
    __syncthreads();

    // fold bias into accumulators
#pragma unroll
    for (int j = 0; j < 4; ++j) {
        float2 bv = *(const float2*)(bias + n0 + wn * 32 + j * 8 + 2 * (l & 3));
#pragma unroll
        for (int fi = 0; fi < 4; ++fi) {
            acc[fi][j][0] += bv.x; acc[fi][j][1] += bv.y;
            acc[fi][j][2] += bv.x; acc[fi][j][3] += bv.y;
        }
    }

    // ---- per-branch rank-16 correction + store (double-buffered staging) ----
    corr_load(0, base, m0, n0, tid); CPCOMMIT();
    corr_load(1, base + 16384, m0, n0, tid); CPCOMMIT();

    for (int br = 0; br < NBR; ++br) {
        uint32_t ep = base + (uint32_t)(br & 1) * 16384;
        if (br < 4) { CPWAIT(1); } else { CPWAIT(0); }
        __syncthreads();

        // B frags (shared across fi halves)
        uint32_t b[2][4];
#pragma unroll
        for (int g = 0; g < 2; ++g) {
            int row = wn * 32 + g * 16 + (l & 15);
            uint32_t ad = ep + 8192 + (uint32_t)((row >> 2) * 128) +
                          (((uint32_t)((row & 3) * 2) + hi16) ^ (uint32_t)((row >> 2) & 1)) * 16;
            ldsm4(b[g], ad);
        }

        float* ob = out + (size_t)br * MM * NN;
#pragma unroll
        for (int h = 0; h < 2; ++h) {
            uint32_t a[2][4];
            float corr[2][4][4];
#pragma unroll
            for (int f2 = 0; f2 < 2; ++f2) {
                int fi = h * 2 + f2;
                int row = wm * 64 + fi * 16 + (l & 15);
                uint32_t ad = ep + (uint32_t)((row >> 2) * 128) +
                              (((uint32_t)((row & 3) * 2) + hi16) ^ (uint32_t)((row >> 2) & 1)) * 16;
                ldsm4(a[f2], ad);
            }
#pragma unroll
            for (int f2 = 0; f2 < 2; ++f2)
#pragma unroll
                for (int nf = 0; nf < 4; ++nf) {
#pragma unroll
                    for (int k = 0; k < 4; ++k) corr[f2][nf][k] = 0.f;
                    mma16816(corr[f2][nf], a[f2], b[nf >> 1][nf & 1], b[nf >> 1][(nf & 1) + 2]);
                }
#pragma unroll
            for (int f2 = 0; f2 < 2; ++f2) {
                int fi = h * 2 + f2;
                int mlo = m0 + wm * 64 + fi * 16 + (l >> 2);
#pragma unroll
                for (int j = 0; j < 4; ++j) {
                    int n = n0 + wn * 32 + j * 8 + 2 * (l & 3);
                    float2 v0{acc[fi][j][0] + corr[f2][j][0], acc[fi][j][1] + corr[f2][j][1]};
                    float2 v1{acc[fi][j][2] + corr[f2][j][2], acc[fi][j][3] + corr[f2][j][3]};
                    *(float2*)(ob + (size_t)mlo * NN + n) = v0;
                    *(float2*)(ob + (size_t)(mlo + 8) * NN + n) = v1;
                }
            }
        }
        __syncthreads();   // all warps done with buffer (br&1)
        if (br + 2 < NBR) { corr_load(br + 2, ep, m0, n0, tid); CPCOMMIT(); }
    }
}

// ------------------- launcher -----------------------------------------------
extern "C" void kernel_launch(void* const* d_in, const int* in_sizes, int n_in,
                              void* d_out, int out_size)
{
    const float* x       = (const float*)d_in[0];
    const float* W       = (const float*)d_in[1];
    const float* b       = (const float*)d_in[2];
    const float* A_sh    = (const float*)d_in[3];
    const float* B_sh    = (const float*)d_in[4];
    const float* A_tasks = (const float*)d_in[5];
    const float* B_tasks = (const float*)d_in[6];
    const float* tscale  = (const float*)d_in[7];
    float* out           = (float*)d_out;

    static bool attr_done = false;
    if (!attr_done) {
        cudaFuncSetAttribute(main_kernel, cudaFuncAttributeMaxDynamicSharedMemorySize, 3 * M_STG);
        cudaFuncSetAttribute(xa_kernel,  cudaFuncAttributeMaxDynamicSharedMemorySize, 3 * XA_STG);
        attr_done = true;
    }

    split_x_k<<<MM * KK / 1024, 256>>>(x);
    split_w_k<<<NN * KK / 1024, 256>>>(W);
    conv_a_k<<<80, 256>>>(A_sh, A_tasks);
    prep_bc_k<<<20, 256>>>(B_sh, B_tasks, tscale);
    xa_kernel<<<MM / 128, 256, 3 * XA_STG>>>();
    main_kernel<<<dim3(NN / 128, MM / 256), 512, 3 * M_STG>>>(b, out);
}